// round 6
// baseline (speedup 1.0000x reference)
#include <cuda_runtime.h>

#define MM 512
#define NN 512
#define NPIX (MM*NN)

typedef unsigned long long u64;

__device__ float2 g_base[NPIX];   // {Xb, yb}
__device__ float2 g_det[NPIX];    // {Xd, yd - Xd}
__device__ unsigned g_minbits, g_maxbits;

#define LOG2E 1.4426950408889634f

#define FMA2(d,a,b,c) asm("fma.rn.f32x2 %0, %1, %2, %3;" : "=l"(d) : "l"(a), "l"(b), "l"(c))
#define ADD2(d,a,b)   asm("add.rn.f32x2 %0, %1, %2;"     : "=l"(d) : "l"(a), "l"(b))
#define MUL2(d,a,b)   asm("mul.rn.f32x2 %0, %1, %2;"     : "=l"(d) : "l"(a), "l"(b))
#define PACK2(d,lo,hi) asm("mov.b64 %0, {%1, %2};" : "=l"(d) : "f"(lo), "f"(hi))
#define UNPACK2(lo,hi,s) asm("mov.b64 {%0, %1}, %2;" : "=f"(lo), "=f"(hi) : "l"(s))
__device__ __forceinline__ float ex2f(float a) {
    float r; asm("ex2.approx.f32 %0, %1;" : "=f"(r) : "f"(a)); return r;
}

__device__ __forceinline__ unsigned f2key(float f) {
    unsigned u = __float_as_uint(f);
    return (u & 0x80000000u) ? ~u : (u | 0x80000000u);
}
__device__ __forceinline__ float key2f(unsigned k) {
    unsigned u = (k & 0x80000000u) ? (k ^ 0x80000000u) : ~k;
    return __uint_as_float(u);
}

__global__ void k_init() { g_minbits = 0xFFFFFFFFu; g_maxbits = 0u; }

// ---- fused: 9x9 box (zero pad, /81) + detail derivation + y min/max ----
__global__ __launch_bounds__(256) void k_pre(const float* __restrict__ X,
                                             const float* __restrict__ Y) {
    __shared__ float2 raw[16][40];
    __shared__ float2 hs[16][32];
    __shared__ unsigned smn[8], smx[8];

    int tx = threadIdx.x, ty = threadIdx.y;
    int bx = blockIdx.x * 32, by = blockIdx.y * 8;
    int tid = ty * 32 + tx;

    for (int k = tid; k < 16 * 40; k += 256) {
        int r = k / 40, c = k % 40;
        int gi = by + r - 4, gj = bx + c - 4;
        float2 v = make_float2(0.f, 0.f);
        if ((unsigned)gi < 512u && (unsigned)gj < 512u) {
            int idx = (gi << 9) + gj;
            v = make_float2(X[idx], Y[idx]);
        }
        raw[r][c] = v;
    }
    __syncthreads();

    for (int k = tid; k < 16 * 32; k += 256) {
        int r = k >> 5, c = k & 31;
        float sx = 0.f, sy = 0.f;
        #pragma unroll
        for (int d = 0; d < 9; ++d) {
            float2 v = raw[r][c + d];
            sx += v.x; sy += v.y;
        }
        hs[r][c] = make_float2(sx, sy);
    }
    __syncthreads();

    float sx = 0.f, sy = 0.f;
    #pragma unroll
    for (int d = 0; d < 9; ++d) {
        float2 v = hs[ty + d][tx];
        sx += v.x; sy += v.y;
    }
    const float inv81 = 1.0f / 81.0f;
    float xb = sx * inv81, yb = sy * inv81;
    float2 ctr = raw[ty + 4][tx + 4];
    float xd = ctr.x - xb;
    float zd = (ctr.y - yb) - xd;
    int idx = ((by + ty) << 9) + bx + tx;
    g_base[idx] = make_float2(xb, yb);
    g_det[idx]  = make_float2(xd, zd);

    // y min/max (each thread contributes exactly its own pixel)
    unsigned key = f2key(ctr.y);
    unsigned mn = key, mx = key;
    #pragma unroll
    for (int o = 16; o; o >>= 1) {
        mn = min(mn, __shfl_xor_sync(0xFFFFFFFFu, mn, o));
        mx = max(mx, __shfl_xor_sync(0xFFFFFFFFu, mx, o));
    }
    if ((tid & 31) == 0) { smn[tid >> 5] = mn; smx[tid >> 5] = mx; }
    __syncthreads();
    if (tid == 0) {
        unsigned m = smn[0], M = smx[0];
        #pragma unroll
        for (int w = 1; w < 8; ++w) { m = min(m, smn[w]); M = max(M, smx[w]); }
        atomicMin(&g_minbits, m);
        atomicMax(&g_maxbits, M);
    }
}

// ================= main bilateral kernel =================
// Thread (tx,ty) handles pixels (by+ty, bx+tx) and (by+ty, bx+tx+32):
// the two f32x2 LANES are the two pixels. Shared tiles store interleaved
// pairs II[r][c] = {v[bx+c-H], v[bx+c-H+32]} so II[r][tx+dj] is one
// conflict-free LDS.64 yielding both lanes' window element at offset dj.
#define BW 26   // 4 + 2*9 rows
#define BC 50   // 32 + 2*9 interleaved slots
#define DR 8    // 4 + 2*2 rows
#define DC 40   // 32 + 2*4 slots

__global__ __launch_bounds__(128) void k_main(const float* __restrict__ R,
                                              float* __restrict__ out) {
    __shared__ float2 bX[22][BC];
    __shared__ float2 bY[22][BC];
    __shared__ float2 dX[DR][DC];
    __shared__ float2 dY[DR][DC];
    __shared__ float sC;

    int tx = threadIdx.x, ty = threadIdx.y;   // 32 x 4
    int bx = blockIdx.x * 64, by = blockIdx.y * 4;
    int tid = ty * 32 + tx;

    if (tid == 0) {
        float mxv = key2f(g_maxbits), mnv = key2f(g_minbits);
        float sigma = R[0] * (mxv - mnv);
        float h = sigma * 0.5f;
        sC = -LOG2E / (h * h);
    }

    for (int k = tid; k < 22 * BC; k += 128) {
        int r = k / BC, c = k % BC;
        int gi = min(max(by + r - 9, 0), 511);
        int gj0 = min(max(bx + c - 9, 0), 511);
        int gj1 = min(max(bx + c + 23, 0), 511);
        float2 v0 = g_base[(gi << 9) + gj0];
        float2 v1 = g_base[(gi << 9) + gj1];
        bX[r][c] = make_float2(v0.x, v1.x);
        bY[r][c] = make_float2(v0.y, v1.y);
    }
    for (int k = tid; k < DR * DC; k += 128) {
        int r = k / DC, c = k % DC;
        int gi = min(max(by + r - 2, 0), 511);
        int gj0 = min(max(bx + c - 4, 0), 511);
        int gj1 = min(max(bx + c + 28, 0), 511);
        float2 v0 = g_det[(gi << 9) + gj0];
        float2 v1 = g_det[(gi << 9) + gj1];
        dX[r][c] = make_float2(v0.x, v1.x);
        dY[r][c] = make_float2(v0.y, v1.y);
    }
    __syncthreads();

    int gi = by + ty;
    int j0 = bx + tx, j1 = j0 + 32;

    // per-lane chunk window
    int kc0 = min((j0 - 1) / 62, 8), kc1 = min((j1 - 1) / 62, 8);
    int cs0 = 62 * kc0, ce0 = min(cs0 + 64, 512);
    int cs1 = 62 * kc1, ce1 = min(cs1 + 64, 512);

    float Cs = sC;
    u64 C2; PACK2(C2, Cs, Cs);

    const float invS1L = LOG2E / 8145.0625f;   // (19*19/4)^2
    const float invS0L = LOG2E / 126.5625f;    // (5*9/4)^2

    // ---------------- Base: 19x19, lanes = 2 pixels ----------------
    float xc0 = bX[ty + 9][tx + 9].x;
    float xc1 = bX[ty + 9][tx + 9].y;
    u64 nxc; { float a0 = -xc0, a1 = -xc1; PACK2(nxc, a0, a1); }

    u64 Lb[19];
    {
        #pragma unroll
        for (int dj = 0; dj < 19; ++dj) {
            int cc = dj - 9;
            float s = -(float)(cc * cc) * invS1L;
            int ja = j0 - 9 + dj, jb = j1 - 9 + dj;
            float l0 = (ja >= cs0 && ja < ce0) ? s : -1e30f;
            float l1 = (jb >= cs1 && jb < ce1) ? s : -1e30f;
            PACK2(Lb[dj], l0, l1);
        }
    }

    u64 g0 = 0, g1 = 0, g2 = 0, g3 = 0, g4 = 0;  // w, wx, wxx, wy, wxy

    #pragma unroll 1
    for (int r = 0; r < 19; ++r) {
        int dd = r - 9;
        float e = ((unsigned)(gi + dd) < 512u) ? ex2f(-(float)(dd * dd) * invS1L) : 0.f;
        const u64* rx = (const u64*)&bX[ty + r][tx];
        const u64* ry = (const u64*)&bY[ty + r][tx];

        u64 p0 = 0, p1 = 0, p2 = 0, p3 = 0, p4 = 0;
        #pragma unroll
        for (int dj = 0; dj < 19; ++dj) {
            u64 vx = rx[dj];
            u64 vy = ry[dj];
            u64 d, t, a;
            ADD2(d, vx, nxc);
            MUL2(t, d, C2);
            FMA2(a, t, d, Lb[dj]);
            float a0, a1; UNPACK2(a0, a1, a);
            float w0 = ex2f(a0), w1 = ex2f(a1);
            u64 w; PACK2(w, w0, w1);
            ADD2(p0, p0, w);
            u64 wx; MUL2(wx, w, vx);
            ADD2(p1, p1, wx);
            FMA2(p2, wx, vx, p2);
            FMA2(p3, w, vy, p3);
            FMA2(p4, wx, vy, p4);
        }
        u64 e2; PACK2(e2, e, e);
        FMA2(g0, e2, p0, g0);
        FMA2(g1, e2, p1, g1);
        FMA2(g2, e2, p2, g2);
        FMA2(g3, e2, p3, g3);
        FMA2(g4, e2, p4, g4);
    }

    float A0, B0, A1, B1;
    {
        float sw0, sw1, sx0, sx1, sxx0, sxx1, sy0, sy1, sxy0, sxy1;
        UNPACK2(sw0, sw1, g0);
        UNPACK2(sx0, sx1, g1);
        UNPACK2(sxx0, sxx1, g2);
        UNPACK2(sy0, sy1, g3);
        UNPACK2(sxy0, sxy1, g4);
        {
            float inv = 1.0f / sw0;
            float mx = sx0 * inv, my = sy0 * inv;
            float var = fmaf(-mx, mx, sxx0 * inv);
            float cov = fmaf(-mx, my, sxy0 * inv);
            A0 = cov / (var + 1e-6f);
            B0 = fmaf(-A0, mx, my);
        }
        {
            float inv = 1.0f / sw1;
            float mx = sx1 * inv, my = sy1 * inv;
            float var = fmaf(-mx, mx, sxx1 * inv);
            float cov = fmaf(-mx, my, sxy1 * inv);
            A1 = cov / (var + 1e-6f);
            B1 = fmaf(-A1, mx, my);
        }
    }

    // ---------------- Detail: 5x9, lanes = 2 pixels ----------------
    float xd0 = dX[ty + 2][tx + 4].x;
    float xd1 = dX[ty + 2][tx + 4].y;
    u64 nxd; { float a0 = -xd0, a1 = -xd1; PACK2(nxd, a0, a1); }

    u64 Ld[9];
    {
        #pragma unroll
        for (int dj = 0; dj < 9; ++dj) {
            int cc = dj - 4;
            float s = -(float)(cc * cc) * invS0L;
            int ja = j0 - 4 + dj, jb = j1 - 4 + dj;
            float l0 = (ja >= cs0 && ja < ce0) ? s : -1e30f;
            float l1 = (jb >= cs1 && jb < ce1) ? s : -1e30f;
            PACK2(Ld[dj], l0, l1);
        }
    }

    u64 s0 = 0, s1 = 0;
    #pragma unroll
    for (int r = 0; r < 5; ++r) {
        int dd = r - 2;
        float e = ((unsigned)(gi + dd) < 512u) ? ex2f(-(float)(dd * dd) * invS0L) : 0.f;
        const u64* rx = (const u64*)&dX[ty + r][tx];
        const u64* ry = (const u64*)&dY[ty + r][tx];
        u64 q0 = 0, q1 = 0;
        #pragma unroll
        for (int dj = 0; dj < 9; ++dj) {
            u64 vx = rx[dj];
            u64 vy = ry[dj];
            u64 d, t, a;
            ADD2(d, vx, nxd);
            MUL2(t, d, C2);
            FMA2(a, t, d, Ld[dj]);
            float a0, a1; UNPACK2(a0, a1, a);
            float w0 = ex2f(a0), w1 = ex2f(a1);
            u64 w; PACK2(w, w0, w1);
            ADD2(q0, q0, w);
            FMA2(q1, w, vy, q1);
        }
        u64 e2; PACK2(e2, e, e);
        FMA2(s0, e2, q0, s0);
        FMA2(s1, e2, q1, s1);
    }
    float swd0, swd1, sz0, sz1;
    UNPACK2(swd0, swd1, s0);
    UNPACK2(sz0, sz1, s1);
    float bd0 = sz0 / swd0;
    float bd1 = sz1 / swd1;

    out[(gi << 9) + j0] = fmaf(A0, xc0, B0 + xd0 + bd0);
    out[(gi << 9) + j1] = fmaf(A1, xc1, B1 + xd1 + bd1);
}

extern "C" void kernel_launch(void* const* d_in, const int* in_sizes, int n_in,
                              void* d_out, int out_size) {
    const float* X = (const float*)d_in[0];
    const float* Y = (const float*)d_in[1];
    const float* R = (const float*)d_in[2];
    float* out = (float*)d_out;

    k_init<<<1, 1>>>();
    k_pre<<<dim3(16, 64), dim3(32, 8)>>>(X, Y);
    k_main<<<dim3(8, 128), dim3(32, 4)>>>(R, out);
}